// round 7
// baseline (speedup 1.0000x reference)
#include <cuda_runtime.h>
#include <cstdint>

// CenterLoss: loss = (sum_i ||x_i - c_{labels_i}||^2) / B + (C-1)*1e-12
// Only the true-label column of the reference's BxC distmat survives the mask;
// masked entries clamp to 1e-12 -> closed-form (C-1)*1e-12 constant.
//
// R7: LDG path plateaued at ~2.1 TB/s across three kernel shapes (per-lane
// L1tex wavefront cost). Switch the bulk traffic to TMA (cp.async.bulk) into
// SMEM: 1 contiguous x copy + 4 gathered center-row copies per block, mbarrier
// completion. Also folds the output-init kernel into the same launch via a
// device-scratch + ticket pattern (single kernel in the graph).

#define CLAMP_MIN 1e-12f
#define CLAMP_MAX 1e12f

#define ROWS_PER_BLOCK 4
#define THREADS 128
#define ROW_FLOATS 512
#define ROW_BYTES (ROW_FLOATS * 4)

__device__ float        g_scratch = 0.0f;
__device__ unsigned int g_count   = 0;

__device__ __forceinline__ uint32_t smem_u32(const void* p) {
    return (uint32_t)__cvta_generic_to_shared(p);
}

__global__ void __launch_bounds__(THREADS)
cl_kernel(const float* __restrict__ x,
          const int* __restrict__ labels,
          const float* __restrict__ centers,
          float* __restrict__ out,
          float inv_b, float const_term, int B, int C, int nblocks)
{
    __shared__ alignas(128) float sx[ROWS_PER_BLOCK * ROW_FLOATS];
    __shared__ alignas(128) float sc[ROWS_PER_BLOCK * ROW_FLOATS];
    __shared__ alignas(8)  unsigned long long mbar;
    __shared__ float warp_part[ROWS_PER_BLOCK];

    const int tid  = threadIdx.x;
    const int lane = tid & 31;
    const int warp = tid >> 5;
    const int row_base = blockIdx.x * ROWS_PER_BLOCK;
    const int nrows = min(ROWS_PER_BLOCK, B - row_base);

    const uint32_t mb = smem_u32(&mbar);

    if (tid == 0) {
        asm volatile("mbarrier.init.shared.b64 [%0], %1;" :: "r"(mb), "r"(1));
    }
    __syncthreads();

    if (tid == 0) {
        const unsigned total_bytes = (unsigned)(2 * nrows * ROW_BYTES);
        asm volatile("mbarrier.arrive.expect_tx.shared.b64 _, [%0], %1;"
                     :: "r"(mb), "r"(total_bytes) : "memory");
        // x rows for this block are contiguous: one bulk copy.
        asm volatile(
            "cp.async.bulk.shared::cluster.global.mbarrier::complete_tx::bytes "
            "[%0], [%1], %2, [%3];"
            :: "r"(smem_u32(sx)),
               "l"(x + (size_t)row_base * ROW_FLOATS),
               "r"((unsigned)(nrows * ROW_BYTES)), "r"(mb)
            : "memory");
        // Gathered center rows: one 2KB bulk copy each.
        #pragma unroll
        for (int r = 0; r < ROWS_PER_BLOCK; r++) {
            if (r < nrows) {
                int lab = labels[row_base + r];
                lab = min(max(lab, 0), C - 1);
                asm volatile(
                    "cp.async.bulk.shared::cluster.global.mbarrier::complete_tx::bytes "
                    "[%0], [%1], %2, [%3];"
                    :: "r"(smem_u32(sc + r * ROW_FLOATS)),
                       "l"(centers + (size_t)lab * ROW_FLOATS),
                       "r"((unsigned)ROW_BYTES), "r"(mb)
                    : "memory");
            }
        }
    }

    // Wait for all copies (phase parity 0; mbarrier used once per launch).
    {
        uint32_t done;
        do {
            asm volatile(
                "{\n\t.reg .pred p;\n\t"
                "mbarrier.try_wait.parity.acquire.cta.shared::cta.b64 p, [%1], 0;\n\t"
                "selp.b32 %0, 1, 0, p;\n\t}"
                : "=r"(done) : "r"(mb) : "memory");
        } while (!done);
    }

    // Warp w handles row w. Conflict-free LDS.128 reads from SMEM.
    float v = 0.0f;
    if (warp < nrows) {
        const float4* xr = (const float4*)sx + warp * (ROW_FLOATS / 4);
        const float4* cr = (const float4*)sc + warp * (ROW_FLOATS / 4);
        float s = 0.0f, d;
        #pragma unroll
        for (int i = 0; i < 4; i++) {
            float4 a = xr[i * 32 + lane];
            float4 c = cr[i * 32 + lane];
            d = a.x - c.x; s += d * d;
            d = a.y - c.y; s += d * d;
            d = a.z - c.z; s += d * d;
            d = a.w - c.w; s += d * d;
        }
        #pragma unroll
        for (int o = 16; o > 0; o >>= 1)
            s += __shfl_xor_sync(0xFFFFFFFFu, s, o);
        // Per-row clamp (no-op at typical magnitudes, kept exact).
        v = fminf(fmaxf(s, CLAMP_MIN), CLAMP_MAX);
    }
    if (lane == 0) warp_part[warp] = (warp < nrows) ? v : 0.0f;
    __syncthreads();

    if (tid == 0) {
        float bsum = warp_part[0] + warp_part[1] + warp_part[2] + warp_part[3];
        atomicAdd(&g_scratch, bsum);
        __threadfence();
        unsigned ticket = atomicAdd(&g_count, 1);
        if (ticket == (unsigned)(nblocks - 1)) {
            // All other blocks' adds are fence-ordered before their ticket
            // increments, which we observed; safe to read.
            float tot = *(volatile float*)&g_scratch;
            *out = tot * inv_b + const_term;
            // Reset for the next graph replay (launches are stream-ordered).
            g_scratch = 0.0f;
            g_count   = 0;
            __threadfence();
        }
    }
}

extern "C" void kernel_launch(void* const* d_in, const int* in_sizes, int n_in,
                              void* d_out, int out_size)
{
    // Inputs (metadata order): x (B*D f32), labels (B int32), centers (C*D f32)
    const float* x       = (const float*)d_in[0];
    const int*   labels  = (const int*)d_in[1];
    const float* centers = (const float*)d_in[2];
    float*       out     = (float*)d_out;

    const int B = in_sizes[1];           // 4096
    const int D = in_sizes[0] / B;       // 512
    const int C = in_sizes[2] / D;       // 10000

    const float const_term = (float)((double)(C - 1) * 1e-12);
    const float inv_b = 1.0f / (float)B;

    const int grid = (B + ROWS_PER_BLOCK - 1) / ROWS_PER_BLOCK;  // 1024

    cl_kernel<<<grid, THREADS>>>(x, labels, centers, out,
                                 inv_b, const_term, B, C, grid);
}